// round 3
// baseline (speedup 1.0000x reference)
#include <cuda_runtime.h>
#include <math.h>

#define N_NODES_MAX 50000
#define N_EDGES_MAX 800000
#define DIM 256
#define INNER 768           // Q|K|V concatenated: 3*256
#define HEADS 8
#define DIM_OUT 32

// ---------------- device scratch (static globals: allocation-free) -------------
__device__ float g_QKV[(size_t)N_NODES_MAX * INNER];   // row n: [q(256) | k(256) | v(256)]
__device__ float g_scores[(size_t)N_EDGES_MAX * HEADS];
__device__ float g_Wf[DIM * INNER];
__device__ float g_bf[INNER];
__device__ int   g_deg[N_NODES_MAX];
__device__ int   g_off[N_NODES_MAX + 1];
__device__ int   g_cur[N_NODES_MAX];
__device__ int   g_perm[N_EDGES_MAX];

// ---------------- weight fusion: Wf[k][c] with c in [0,768) -------------------
__global__ void prep_w_kernel(const float* __restrict__ Wq, const float* __restrict__ bq,
                              const float* __restrict__ Wk, const float* __restrict__ bk,
                              const float* __restrict__ Wv, const float* __restrict__ bv) {
    int idx = blockIdx.x * blockDim.x + threadIdx.x;
    if (idx < DIM * INNER) {
        int k = idx / INNER, c = idx - k * INNER;
        float w;
        if (c < 256)       w = Wq[k * 256 + c];
        else if (c < 512)  w = Wk[k * 256 + (c - 256)];
        else               w = Wv[k * 256 + (c - 512)];
        g_Wf[idx] = w;
    }
    if (idx < INNER) {
        float b;
        if (idx < 256)      b = bq[idx];
        else if (idx < 512) b = bk[idx - 256];
        else                b = bv[idx - 512];
        g_bf[idx] = b;
    }
}

// ---------------- fused QKV GEMM: C[M,768] = x[M,256] @ Wf + bf ---------------
// BM=128, BN=64, BK=16, 256 threads, 8x4 micro-tile per thread.
#define BM 128
#define BN 64
#define BK 16
__global__ __launch_bounds__(256) void gemm_qkv_kernel(const float* __restrict__ A, int M) {
    __shared__ float As[BK][BM];
    __shared__ float Bs[BK][BN];
    const int tid = threadIdx.x;
    const int tx = tid & 15;    // N dim: 16*4 = 64
    const int ty = tid >> 4;    // M dim: 16*8 = 128
    const int m0 = blockIdx.x * BM;
    const int n0 = blockIdx.y * BN;

    float acc[8][4];
#pragma unroll
    for (int i = 0; i < 8; ++i)
#pragma unroll
        for (int j = 0; j < 4; ++j) acc[i][j] = 0.f;

    for (int k0 = 0; k0 < DIM; k0 += BK) {
        // load A tile 128x16 (transposed into As[k][m])
#pragma unroll
        for (int pass = 0; pass < 2; ++pass) {
            int r = (tid >> 2) + pass * 64;
            int c = (tid & 3) * 4;
            float4 av = make_float4(0.f, 0.f, 0.f, 0.f);
            int gm = m0 + r;
            if (gm < M) av = *(const float4*)(A + (size_t)gm * DIM + k0 + c);
            As[c + 0][r] = av.x; As[c + 1][r] = av.y;
            As[c + 2][r] = av.z; As[c + 3][r] = av.w;
        }
        // load B tile 16x64
        {
            int r = tid >> 4;
            int c = (tid & 15) * 4;
            *(float4*)&Bs[r][c] = *(const float4*)(g_Wf + (size_t)(k0 + r) * INNER + n0 + c);
        }
        __syncthreads();
#pragma unroll
        for (int kk = 0; kk < BK; ++kk) {
            float a[8], b[4];
            *(float4*)&a[0] = *(float4*)&As[kk][ty * 8];
            *(float4*)&a[4] = *(float4*)&As[kk][ty * 8 + 4];
            *(float4*)&b[0] = *(float4*)&Bs[kk][tx * 4];
#pragma unroll
            for (int i = 0; i < 8; ++i)
#pragma unroll
                for (int j = 0; j < 4; ++j) acc[i][j] = fmaf(a[i], b[j], acc[i][j]);
        }
        __syncthreads();
    }
    // epilogue: + bias, store float4
    float4 b4 = *(const float4*)(g_bf + n0 + tx * 4);
#pragma unroll
    for (int i = 0; i < 8; ++i) {
        int gm = m0 + ty * 8 + i;
        if (gm < M) {
            float4 o;
            o.x = acc[i][0] + b4.x; o.y = acc[i][1] + b4.y;
            o.z = acc[i][2] + b4.z; o.w = acc[i][3] + b4.w;
            *(float4*)(g_QKV + (size_t)gm * INNER + n0 + tx * 4) = o;
        }
    }
}

// ---------------- CSR build ----------------------------------------------------
__global__ void zero_deg_kernel(int n) {
    int i = blockIdx.x * blockDim.x + threadIdx.x;
    if (i < n) g_deg[i] = 0;
}

__global__ void hist_kernel(const int* __restrict__ dst, int E) {
    int e = blockIdx.x * blockDim.x + threadIdx.x;
    if (e < E) atomicAdd(&g_deg[dst[e]], 1);
}

// single-block exclusive scan of g_deg[0..n) -> g_off, g_cur; g_off[n] = total
__global__ __launch_bounds__(1024) void scan_kernel(int n) {
    __shared__ int sh[1024];
    __shared__ int carry_s;
    int t = threadIdx.x;
    if (t == 0) carry_s = 0;
    __syncthreads();
    for (int base = 0; base < n; base += 1024) {
        int v = (base + t < n) ? g_deg[base + t] : 0;
        int x = v;
#pragma unroll
        for (int d = 1; d < 1024; d <<= 1) {
            sh[t] = x;
            __syncthreads();
            if (t >= d) x += sh[t - d];
            __syncthreads();
        }
        int carry = carry_s;
        int excl = carry + x - v;
        if (base + t < n) { g_off[base + t] = excl; g_cur[base + t] = excl; }
        __syncthreads();
        if (t == 1023) carry_s = carry + x;
        __syncthreads();
    }
    if (t == 0) g_off[n] = carry_s;
}

__global__ void scatter_kernel(const int* __restrict__ dst, int E) {
    int e = blockIdx.x * blockDim.x + threadIdx.x;
    if (e < E) {
        int p = atomicAdd(&g_cur[dst[e]], 1);
        g_perm[p] = e;
    }
}

// ---------------- fused attention: one warp per dst node ----------------------
// lane l owns output dims [8l, 8l+8); head(l) = l>>2 (4 lanes per head).
__global__ __launch_bounds__(256) void attn_kernel(const int* __restrict__ src,
                                                   float* __restrict__ out, int n_nodes) {
    int gwarp = (blockIdx.x * blockDim.x + threadIdx.x) >> 5;
    int lane = threadIdx.x & 31;
    if (gwarp >= n_nodes) return;
    const int node = gwarp;
    const int rs = g_off[node];
    const int re = g_off[node + 1];
    const int head = lane >> 2;

    const float4* kp = (const float4*)(g_QKV + (size_t)node * INNER + 256 + lane * 8);
    float4 k0 = kp[0], k1 = kp[1];

    float m = -INFINITY;
    // pass 1: scores + running per-head max
    for (int i = rs; i < re; ++i) {
        int e = g_perm[i];
        int s = src[e];                       // same addr for whole warp -> broadcast
        const float4* qp = (const float4*)(g_QKV + (size_t)s * INNER + lane * 8);
        float4 q0 = qp[0], q1 = qp[1];
        float p = q0.x * k0.x + q0.y * k0.y + q0.z * k0.z + q0.w * k0.w
                + q1.x * k1.x + q1.y * k1.y + q1.z * k1.z + q1.w * k1.w;
        p += __shfl_xor_sync(0xffffffffu, p, 1);
        p += __shfl_xor_sync(0xffffffffu, p, 2);
        float sc = p * 0.17677669529663689f;  // 1/sqrt(32)
        m = fmaxf(m, sc);
        if ((lane & 3) == 0) g_scores[(size_t)i * HEADS + head] = sc;
    }

    // pass 2: z = sum exp, acc = sum v * exp  (normalize once at the end)
    float z = 0.f;
    float4 a0 = make_float4(0.f, 0.f, 0.f, 0.f);
    float4 a1 = make_float4(0.f, 0.f, 0.f, 0.f);
    for (int i = rs; i < re; ++i) {
        int e = g_perm[i];
        int s = src[e];
        float sc = g_scores[(size_t)i * HEADS + head];
        float w = __expf(sc - m);
        z += w;
        const float4* vp = (const float4*)(g_QKV + (size_t)s * INNER + 512 + lane * 8);
        float4 v0 = vp[0], v1 = vp[1];
        a0.x = fmaf(v0.x, w, a0.x); a0.y = fmaf(v0.y, w, a0.y);
        a0.z = fmaf(v0.z, w, a0.z); a0.w = fmaf(v0.w, w, a0.w);
        a1.x = fmaf(v1.x, w, a1.x); a1.y = fmaf(v1.y, w, a1.y);
        a1.z = fmaf(v1.z, w, a1.z); a1.w = fmaf(v1.w, w, a1.w);
    }
    float inv = 1.f / fmaxf(z, 1e-16f);
    float4 o0 = make_float4(a0.x * inv, a0.y * inv, a0.z * inv, a0.w * inv);
    float4 o1 = make_float4(a1.x * inv, a1.y * inv, a1.z * inv, a1.w * inv);
    float4* op = (float4*)(out + (size_t)node * 256 + lane * 8);
    op[0] = o0;
    op[1] = o1;
}

// ---------------- launch -------------------------------------------------------
extern "C" void kernel_launch(void* const* d_in, const int* in_sizes, int n_in,
                              void* d_out, int out_size) {
    const float* x  = (const float*)d_in[0];
    const float* Wq = (const float*)d_in[1];
    const float* bq = (const float*)d_in[2];
    const float* Wk = (const float*)d_in[3];
    const float* bk = (const float*)d_in[4];
    const float* Wv = (const float*)d_in[5];
    const float* bv = (const float*)d_in[6];
    const int* src  = (const int*)d_in[7];
    const int* dst  = (const int*)d_in[8];
    float* out = (float*)d_out;

    const int N = in_sizes[0] / DIM;   // 50000
    const int E = in_sizes[7];         // 800000

    // 1. fuse weights
    prep_w_kernel<<<(DIM * INNER + 255) / 256, 256>>>(Wq, bq, Wk, bk, Wv, bv);

    // 2. fused QKV projection
    dim3 ggrid((N + BM - 1) / BM, INNER / BN);
    gemm_qkv_kernel<<<ggrid, 256>>>(x, N);

    // 3. CSR by dst
    zero_deg_kernel<<<(N + 255) / 256, 256>>>(N);
    hist_kernel<<<(E + 255) / 256, 256>>>(dst, E);
    scan_kernel<<<1, 1024>>>(N);
    scatter_kernel<<<(E + 255) / 256, 256>>>(dst, E);

    // 4. warp-per-node attention (scores -> softmax -> weighted aggregate)
    attn_kernel<<<(N + 7) / 8, 256>>>(src, out, N);
}

// round 8
// speedup vs baseline: 1.5216x; 1.5216x over previous
#include <cuda_runtime.h>
#include <cuda_bf16.h>
#include <math.h>
#include <stdint.h>

#define DIM 256
#define INNER 768           // Q|K|V concatenated
#define HEADS 8
#define NMAX 50000
#define EMAX 800000

// ---------------- device scratch (static: allocation-free) --------------------
__device__ float          g_QKV[(size_t)NMAX * INNER];   // row: [q(256)|k(256)|v(256)]
__device__ __nv_bfloat16  g_xh[(size_t)NMAX * DIM];
__device__ __nv_bfloat16  g_xl[(size_t)NMAX * DIM];
__device__ __nv_bfloat16  g_wth[INNER * DIM];            // W^T hi: [n][k]
__device__ __nv_bfloat16  g_wtl[INNER * DIM];            // W^T lo
__device__ float          g_bf[INNER];
__device__ int            g_deg[NMAX];
__device__ int            g_off[NMAX + 1];
__device__ int            g_cur[NMAX];
__device__ int            g_sperm[EMAX];   // src node id, permuted into dst-CSR order

__device__ __forceinline__ uint32_t smem_u32(const void* p) {
    uint32_t a;
    asm("{ .reg .u64 t; cvta.to.shared.u64 t, %1; cvt.u32.u64 %0, t; }" : "=r"(a) : "l"(p));
    return a;
}

// ---------------- prep: W^T hi/lo + bias + zero deg ---------------------------
__global__ void prep_w_kernel(const float* __restrict__ Wq, const float* __restrict__ bq,
                              const float* __restrict__ Wk, const float* __restrict__ bk,
                              const float* __restrict__ Wv, const float* __restrict__ bv,
                              int n_nodes) {
    int idx = blockIdx.x * blockDim.x + threadIdx.x;
    if (idx < INNER * DIM) {
        int n = idx >> 8, k = idx & 255;
        float w = (n < 256) ? Wq[k * 256 + n]
                : (n < 512) ? Wk[k * 256 + (n - 256)]
                            : Wv[k * 256 + (n - 512)];
        __nv_bfloat16 h = __float2bfloat16(w);
        __nv_bfloat16 l = __float2bfloat16(w - __bfloat162float(h));
        g_wth[idx] = h;   // layout [n][k] == idx
        g_wtl[idx] = l;
    }
    if (idx < INNER) {
        g_bf[idx] = (idx < 256) ? bq[idx] : (idx < 512) ? bk[idx - 256] : bv[idx - 512];
    }
    if (idx < n_nodes) g_deg[idx] = 0;
}

// ---------------- x -> bf16 hi/lo ----------------------------------------------
__global__ void conv_x_kernel(const float* __restrict__ x, int total4) {
    int i = blockIdx.x * blockDim.x + threadIdx.x;
    if (i >= total4) return;
    float4 v = ((const float4*)x)[i];
    float f[4] = {v.x, v.y, v.z, v.w};
    __nv_bfloat16 h[4], l[4];
#pragma unroll
    for (int j = 0; j < 4; ++j) {
        h[j] = __float2bfloat16(f[j]);
        l[j] = __float2bfloat16(f[j] - __bfloat162float(h[j]));
    }
    __nv_bfloat162* ph = (__nv_bfloat162*)g_xh + 2 * (size_t)i;
    __nv_bfloat162* pl = (__nv_bfloat162*)g_xl + 2 * (size_t)i;
    ph[0] = __halves2bfloat162(h[0], h[1]);
    ph[1] = __halves2bfloat162(h[2], h[3]);
    pl[0] = __halves2bfloat162(l[0], l[1]);
    pl[1] = __halves2bfloat162(l[2], l[3]);
}

// ---------------- mma.sync bf16 GEMM: g_QKV[M,768] = x @ W + b ----------------
// CTA 128x128, BK=32, 8 warps (2x4), warp tile 64x32.
// Split fp32: C = Ah*Bh + Ah*Bl + Al*Bh.
#define BK 32
#define LDS 40    // smem row stride (bf16): 32 + 8 pad -> 80B

#define LDMX4(r0, r1, r2, r3, a)                                              \
    asm volatile("ldmatrix.sync.aligned.m8n8.x4.shared.b16 {%0,%1,%2,%3}, [%4];" \
        : "=r"(r0), "=r"(r1), "=r"(r2), "=r"(r3) : "r"(a))

#define MMA16816(c, A, B)                                                     \
    asm volatile("mma.sync.aligned.m16n8k16.row.col.f32.bf16.bf16.f32 "       \
        "{%0,%1,%2,%3}, {%4,%5,%6,%7}, {%8,%9}, {%0,%1,%2,%3};"               \
        : "+f"((c)[0]), "+f"((c)[1]), "+f"((c)[2]), "+f"((c)[3])              \
        : "r"((A)[0]), "r"((A)[1]), "r"((A)[2]), "r"((A)[3]),                 \
          "r"((B)[0]), "r"((B)[1]))

__global__ __launch_bounds__(256) void gemm_mma_kernel(int Nn) {
    __shared__ __nv_bfloat16 As_h[128 * LDS];
    __shared__ __nv_bfloat16 As_l[128 * LDS];
    __shared__ __nv_bfloat16 Bs_h[128 * LDS];
    __shared__ __nv_bfloat16 Bs_l[128 * LDS];

    const int t = threadIdx.x;
    const int lane = t & 31;
    const int w = t >> 5;
    const int wm = (w & 1) * 64;     // warp row offset in CTA tile
    const int wn = (w >> 1) * 32;    // warp col offset
    const int m0 = blockIdx.x * 128;
    const int n0 = blockIdx.y * 128;

    float acc[4][4][4];
#pragma unroll
    for (int i = 0; i < 4; ++i)
#pragma unroll
        for (int j = 0; j < 4; ++j)
#pragma unroll
            for (int c = 0; c < 4; ++c) acc[i][j][c] = 0.f;

    const uint32_t ah_b = smem_u32(As_h), al_b = smem_u32(As_l);
    const uint32_t bh_b = smem_u32(Bs_h), bl_b = smem_u32(Bs_l);

    // gmem->smem indices: 2 threads per row, 16 bf16 (32B) each
    const int ldr = t >> 1;              // 0..127
    const int ldc = (t & 1) * 16;        // 0 or 16
    const int s_off = ldr * LDS + ldc;

    for (int k0 = 0; k0 < DIM; k0 += BK) {
        // A (predicated on M tail)
        {
            bool ok = (m0 + ldr) < Nn;
            const uint4* gh = (const uint4*)(g_xh + (size_t)(m0 + ldr) * DIM + k0 + ldc);
            const uint4* gl = (const uint4*)(g_xl + (size_t)(m0 + ldr) * DIM + k0 + ldc);
            uint4 z = make_uint4(0, 0, 0, 0);
            uint4 h0 = ok ? gh[0] : z, h1 = ok ? gh[1] : z;
            uint4 l0 = ok ? gl[0] : z, l1 = ok ? gl[1] : z;
            *(uint4*)(As_h + s_off) = h0; *(uint4*)(As_h + s_off + 8) = h1;
            *(uint4*)(As_l + s_off) = l0; *(uint4*)(As_l + s_off + 8) = l1;
        }
        // B (full)
        {
            const uint4* gh = (const uint4*)(g_wth + (size_t)(n0 + ldr) * DIM + k0 + ldc);
            const uint4* gl = (const uint4*)(g_wtl + (size_t)(n0 + ldr) * DIM + k0 + ldc);
            uint4 h0 = gh[0], h1 = gh[1];
            uint4 l0 = gl[0], l1 = gl[1];
            *(uint4*)(Bs_h + s_off) = h0; *(uint4*)(Bs_h + s_off + 8) = h1;
            *(uint4*)(Bs_l + s_off) = l0; *(uint4*)(Bs_l + s_off + 8) = l1;
        }
        __syncthreads();

#pragma unroll
        for (int kk = 0; kk < BK; kk += 16) {
            // A fragments: 4 m-tiles x (hi, lo)
            uint32_t ah[4][4], al[4][4];
            {
                uint32_t aoff = ((wm + (lane & 15)) * LDS + kk + (lane >> 4) * 8) * 2;
#pragma unroll
                for (int mt = 0; mt < 4; ++mt) {
                    uint32_t adr = aoff + mt * 16 * LDS * 2;
                    LDMX4(ah[mt][0], ah[mt][1], ah[mt][2], ah[mt][3], ah_b + adr);
                    LDMX4(al[mt][0], al[mt][1], al[mt][2], al[mt][3], al_b + adr);
                }
            }
            // B fragments: 4 n-tiles x (hi, lo); x4 loads cover 2 n-tiles each
            uint32_t bh[4][2], bl[4][2];
            {
                int g = lane >> 3;
                uint32_t boff = ((wn + (g >> 1) * 8 + (lane & 7)) * LDS + kk + (g & 1) * 8) * 2;
#pragma unroll
                for (int p = 0; p < 2; ++p) {
                    uint32_t adr = boff + p * 16 * LDS * 2;
                    LDMX4(bh[2 * p][0], bh[2 * p][1], bh[2 * p + 1][0], bh[2 * p + 1][1], bh_b + adr);
                    LDMX4(bl[2 * p][0], bl[2 * p][1], bl[2 * p + 1][0], bl[2 * p + 1][1], bl_b + adr);
                }
            }
#pragma unroll
            for (int mt = 0; mt < 4; ++mt)
#pragma unroll
                for (int nt = 0; nt < 4; ++nt) {
                    MMA16816(acc[mt][nt], ah[mt], bh[nt]);
                    MMA16816(acc[mt][nt], ah[mt], bl[nt]);
                    MMA16816(acc[mt][nt], al[mt], bh[nt]);
                }
        }
        __syncthreads();
    }

    // epilogue: + bias, store float2 per fragment half
#pragma unroll
    for (int mt = 0; mt < 4; ++mt) {
#pragma unroll
        for (int nt = 0; nt < 4; ++nt) {
            int row = m0 + wm + mt * 16 + (lane >> 2);
            int col = n0 + wn + nt * 8 + (lane & 3) * 2;
            float2 bv = *(const float2*)(g_bf + col);
            if (row < Nn) {
                float2 o; o.x = acc[mt][nt][0] + bv.x; o.y = acc[mt][nt][1] + bv.y;
                *(float2*)(g_QKV + (size_t)row * INNER + col) = o;
            }
            if (row + 8 < Nn) {
                float2 o; o.x = acc[mt][nt][2] + bv.x; o.y = acc[mt][nt][3] + bv.y;
                *(float2*)(g_QKV + (size_t)(row + 8) * INNER + col) = o;
            }
        }
    }
}

// ---------------- CSR build ----------------------------------------------------
__global__ void hist_kernel(const int* __restrict__ dst, int E) {
    int e = blockIdx.x * blockDim.x + threadIdx.x;
    if (e < E) atomicAdd(&g_deg[dst[e]], 1);
}

__global__ __launch_bounds__(1024) void scan_kernel(int n) {
    __shared__ int sh[1024];
    __shared__ int carry_s;
    int t = threadIdx.x;
    if (t == 0) carry_s = 0;
    __syncthreads();
    for (int base = 0; base < n; base += 1024) {
        int v = (base + t < n) ? g_deg[base + t] : 0;
        int x = v;
#pragma unroll
        for (int d = 1; d < 1024; d <<= 1) {
            sh[t] = x;
            __syncthreads();
            if (t >= d) x += sh[t - d];
            __syncthreads();
        }
        int carry = carry_s;
        int excl = carry + x - v;
        if (base + t < n) { g_off[base + t] = excl; g_cur[base + t] = excl; }
        __syncthreads();
        if (t == 1023) carry_s = carry + x;
        __syncthreads();
    }
    if (t == 0) g_off[n] = carry_s;
}

// store src node id directly (kills one indirection in the attention hot loop)
__global__ void scatter_kernel(const int* __restrict__ dst, const int* __restrict__ src,
                               int E) {
    int e = blockIdx.x * blockDim.x + threadIdx.x;
    if (e < E) {
        int p = atomicAdd(&g_cur[dst[e]], 1);
        g_sperm[p] = src[e];
    }
}

// ---------------- single-pass online-softmax attention ------------------------
// one warp per dst node; lane l owns output dims [8l,8l+8); head = l>>2.
__global__ __launch_bounds__(256) void attn_kernel(float* __restrict__ out, int n_nodes) {
    int gwarp = (blockIdx.x * blockDim.x + threadIdx.x) >> 5;
    int lane = threadIdx.x & 31;
    if (gwarp >= n_nodes) return;
    const int rs = g_off[gwarp];
    const int re = g_off[gwarp + 1];

    const float4* kp = (const float4*)(g_QKV + (size_t)gwarp * INNER + 256 + lane * 8);
    const float4 k0 = kp[0], k1 = kp[1];

    float m = -INFINITY, z = 0.f;
    float4 a0 = make_float4(0.f, 0.f, 0.f, 0.f);
    float4 a1 = make_float4(0.f, 0.f, 0.f, 0.f);

    // prefetch first index: the index load heads the dependent chain
    int s = (rs < re) ? __ldg(&g_sperm[rs]) : 0;

    for (int i = rs; i < re; ++i) {
        int s_next = (i + 1 < re) ? __ldg(&g_sperm[i + 1]) : 0;

        const float4* qp = (const float4*)(g_QKV + (size_t)s * INNER + lane * 8);
        const float4* vp = (const float4*)(g_QKV + (size_t)s * INNER + 512 + lane * 8);
        float4 q0 = qp[0], q1 = qp[1];
        float4 v0 = vp[0], v1 = vp[1];

        float p = q0.x * k0.x + q0.y * k0.y + q0.z * k0.z + q0.w * k0.w
                + q1.x * k1.x + q1.y * k1.y + q1.z * k1.z + q1.w * k1.w;
        p += __shfl_xor_sync(0xffffffffu, p, 1);
        p += __shfl_xor_sync(0xffffffffu, p, 2);
        float sc = p * 0.17677669529663689f;   // 1/sqrt(32)

        float nm = fmaxf(m, sc);
        float scale = __expf(m - nm);          // first iter: exp(-inf)=0
        float wgt = __expf(sc - nm);
        m = nm;
        z = fmaf(z, scale, wgt);
        a0.x = fmaf(a0.x, scale, v0.x * wgt); a0.y = fmaf(a0.y, scale, v0.y * wgt);
        a0.z = fmaf(a0.z, scale, v0.z * wgt); a0.w = fmaf(a0.w, scale, v0.w * wgt);
        a1.x = fmaf(a1.x, scale, v1.x * wgt); a1.y = fmaf(a1.y, scale, v1.y * wgt);
        a1.z = fmaf(a1.z, scale, v1.z * wgt); a1.w = fmaf(a1.w, scale, v1.w * wgt);

        s = s_next;
    }
    float inv = 1.f / fmaxf(z, 1e-16f);
    float4* op = (float4*)(out + (size_t)gwarp * 256 + lane * 8);
    op[0] = make_float4(a0.x * inv, a0.y * inv, a0.z * inv, a0.w * inv);
    op[1] = make_float4(a1.x * inv, a1.y * inv, a1.z * inv, a1.w * inv);
}

// ---------------- launch -------------------------------------------------------
extern "C" void kernel_launch(void* const* d_in, const int* in_sizes, int n_in,
                              void* d_out, int out_size) {
    const float* x  = (const float*)d_in[0];
    const float* Wq = (const float*)d_in[1];
    const float* bq = (const float*)d_in[2];
    const float* Wk = (const float*)d_in[3];
    const float* bk = (const float*)d_in[4];
    const float* Wv = (const float*)d_in[5];
    const float* bv = (const float*)d_in[6];
    const int* src  = (const int*)d_in[7];
    const int* dst  = (const int*)d_in[8];
    float* out = (float*)d_out;

    const int N = in_sizes[0] / DIM;
    const int E = in_sizes[7];

    // weights + bias + deg-zero; x split
    prep_w_kernel<<<(INNER * DIM + 255) / 256, 256>>>(Wq, bq, Wk, bk, Wv, bv, N);
    conv_x_kernel<<<(N * (DIM / 4) + 255) / 256, 256>>>(x, N * (DIM / 4));

    // CSR by dst
    hist_kernel<<<(E + 255) / 256, 256>>>(dst, E);
    scan_kernel<<<1, 1024>>>(N);
    scatter_kernel<<<(E + 255) / 256, 256>>>(dst, src, E);

    // fused QKV projection on tensor cores (mma.sync)
    dim3 ggrid((N + 127) / 128, INNER / 128);
    gemm_mma_kernel<<<ggrid, 256>>>(N);

    // warp-per-node single-pass attention
    attn_kernel<<<(N + 7) / 8, 256>>>(out, N);
}

// round 9
// speedup vs baseline: 1.7733x; 1.1654x over previous
#include <cuda_runtime.h>
#include <cuda_bf16.h>
#include <math.h>
#include <stdint.h>

#define DIM 256
#define INNER 768           // Q|K|V concatenated
#define HEADS 8
#define NMAX 50000
#define EMAX 800000

// ---------------- device scratch (static: allocation-free) --------------------
__device__ float          g_QKV[(size_t)NMAX * INNER];   // row: [q(256)|k(256)|v(256)]
__device__ __nv_bfloat16  g_xh[(size_t)NMAX * DIM];
__device__ __nv_bfloat16  g_xl[(size_t)NMAX * DIM];
__device__ __nv_bfloat16  g_wth[INNER * DIM];            // W^T hi: [n][k]
__device__ __nv_bfloat16  g_wtl[INNER * DIM];            // W^T lo
__device__ float          g_bf[INNER];
__device__ __align__(16) int g_deg[NMAX];
__device__ int            g_off[NMAX + 1];
__device__ int            g_cur[NMAX];
__device__ int            g_sperm[EMAX];   // src node id, permuted into dst-CSR order

__device__ __forceinline__ uint32_t smem_u32(const void* p) {
    uint32_t a;
    asm("{ .reg .u64 t; cvta.to.shared.u64 t, %1; cvt.u32.u64 %0, t; }" : "=r"(a) : "l"(p));
    return a;
}

// ---------------- prep: W^T hi/lo + bias + zero deg ---------------------------
__global__ void prep_w_kernel(const float* __restrict__ Wq, const float* __restrict__ bq,
                              const float* __restrict__ Wk, const float* __restrict__ bk,
                              const float* __restrict__ Wv, const float* __restrict__ bv,
                              int n_nodes) {
    int idx = blockIdx.x * blockDim.x + threadIdx.x;
    if (idx < INNER * DIM) {
        int n = idx >> 8, k = idx & 255;
        float w = (n < 256) ? Wq[k * 256 + n]
                : (n < 512) ? Wk[k * 256 + (n - 256)]
                            : Wv[k * 256 + (n - 512)];
        __nv_bfloat16 h = __float2bfloat16(w);
        __nv_bfloat16 l = __float2bfloat16(w - __bfloat162float(h));
        g_wth[idx] = h;   // layout [n][k] == idx
        g_wtl[idx] = l;
    }
    if (idx < INNER) {
        g_bf[idx] = (idx < 256) ? bq[idx] : (idx < 512) ? bk[idx - 256] : bv[idx - 512];
    }
    if (idx < n_nodes) g_deg[idx] = 0;
}

// ---------------- x -> bf16 hi/lo ----------------------------------------------
__global__ void conv_x_kernel(const float* __restrict__ x, int total4) {
    int i = blockIdx.x * blockDim.x + threadIdx.x;
    if (i >= total4) return;
    float4 v = ((const float4*)x)[i];
    float f[4] = {v.x, v.y, v.z, v.w};
    __nv_bfloat16 h[4], l[4];
#pragma unroll
    for (int j = 0; j < 4; ++j) {
        h[j] = __float2bfloat16(f[j]);
        l[j] = __float2bfloat16(f[j] - __bfloat162float(h[j]));
    }
    __nv_bfloat162* ph = (__nv_bfloat162*)g_xh + 2 * (size_t)i;
    __nv_bfloat162* pl = (__nv_bfloat162*)g_xl + 2 * (size_t)i;
    ph[0] = __halves2bfloat162(h[0], h[1]);
    ph[1] = __halves2bfloat162(h[2], h[3]);
    pl[0] = __halves2bfloat162(l[0], l[1]);
    pl[1] = __halves2bfloat162(l[2], l[3]);
}

// ---------------- mma.sync bf16 GEMM: g_QKV[M,768] = x @ W + b ----------------
// CTA 128x128, BK=32, 8 warps (2x4), warp tile 64x32.
// Split fp32: C = Ah*Bh + Ah*Bl + Al*Bh.  cp.async 2-stage pipeline.
#define BK 32
#define LDS 40            // smem row stride (bf16): 32 + 8 pad -> 80B
#define ARR_BYTES (128 * LDS * 2)      // 10240
#define OFF_AH 0
#define OFF_AL ARR_BYTES
#define OFF_BH (2 * ARR_BYTES)
#define OFF_BL (3 * ARR_BYTES)
#define STAGE_BYTES (4 * ARR_BYTES)    // 40960
#define GT_SMEM (2 * STAGE_BYTES)      // 81920

#define LDMX4(r0, r1, r2, r3, a)                                              \
    asm volatile("ldmatrix.sync.aligned.m8n8.x4.shared.b16 {%0,%1,%2,%3}, [%4];" \
        : "=r"(r0), "=r"(r1), "=r"(r2), "=r"(r3) : "r"(a))

#define MMA16816(c, A, B)                                                     \
    asm volatile("mma.sync.aligned.m16n8k16.row.col.f32.bf16.bf16.f32 "       \
        "{%0,%1,%2,%3}, {%4,%5,%6,%7}, {%8,%9}, {%0,%1,%2,%3};"               \
        : "+f"((c)[0]), "+f"((c)[1]), "+f"((c)[2]), "+f"((c)[3])              \
        : "r"((A)[0]), "r"((A)[1]), "r"((A)[2]), "r"((A)[3]),                 \
          "r"((B)[0]), "r"((B)[1]))

__device__ __forceinline__ void cp16(uint32_t d, const void* s, int sz) {
    asm volatile("cp.async.cg.shared.global [%0], [%1], 16, %2;"
                 :: "r"(d), "l"(s), "r"(sz));
}
#define CP_COMMIT() asm volatile("cp.async.commit_group;" ::: "memory")
#define CP_WAIT1()  asm volatile("cp.async.wait_group 1;" ::: "memory")

__global__ __launch_bounds__(256) void gemm_mma_kernel(int Nn) {
    extern __shared__ __align__(16) char dynsmem[];

    const int t = threadIdx.x;
    const int lane = t & 31;
    const int w = t >> 5;
    const int wm = (w & 1) * 64;     // warp row offset in CTA tile
    const int wn = (w >> 1) * 32;    // warp col offset
    const int m0 = blockIdx.x * 128;
    const int n0 = blockIdx.y * 128;
    const uint32_t sbase = smem_u32(dynsmem);

    float acc[4][4][4];
#pragma unroll
    for (int i = 0; i < 4; ++i)
#pragma unroll
        for (int j = 0; j < 4; ++j)
#pragma unroll
            for (int c = 0; c < 4; ++c) acc[i][j][c] = 0.f;

    // gmem->smem indices: 2 threads per row, 16 bf16 (32B = 2 cp.async) each
    const int ldr = t >> 1;               // 0..127
    const int ldc = (t & 1) * 16;         // 0 or 16
    const int s_byte = (ldr * LDS + ldc) * 2;
    const int asz = ((m0 + ldr) < Nn) ? 16 : 0;   // zero-fill M tail

    const __nv_bfloat16* gah = g_xh  + (size_t)(m0 + ldr) * DIM + ldc;
    const __nv_bfloat16* gal = g_xl  + (size_t)(m0 + ldr) * DIM + ldc;
    const __nv_bfloat16* gbh = g_wth + (size_t)(n0 + ldr) * DIM + ldc;
    const __nv_bfloat16* gbl = g_wtl + (size_t)(n0 + ldr) * DIM + ldc;

#define LOAD_STAGE(stg, k0) do {                                              \
        uint32_t sb_ = sbase + (stg) * STAGE_BYTES;                           \
        cp16(sb_ + OFF_AH + s_byte,      gah + (k0),     asz);                \
        cp16(sb_ + OFF_AH + s_byte + 16, gah + (k0) + 8, asz);                \
        cp16(sb_ + OFF_AL + s_byte,      gal + (k0),     asz);                \
        cp16(sb_ + OFF_AL + s_byte + 16, gal + (k0) + 8, asz);                \
        cp16(sb_ + OFF_BH + s_byte,      gbh + (k0),     16);                 \
        cp16(sb_ + OFF_BH + s_byte + 16, gbh + (k0) + 8, 16);                 \
        cp16(sb_ + OFF_BL + s_byte,      gbl + (k0),     16);                 \
        cp16(sb_ + OFF_BL + s_byte + 16, gbl + (k0) + 8, 16);                 \
    } while (0)

    LOAD_STAGE(0, 0);
    CP_COMMIT();

#pragma unroll 1
    for (int it = 0; it < DIM / BK; ++it) {
        if (it + 1 < DIM / BK) LOAD_STAGE((it + 1) & 1, (it + 1) * BK);
        CP_COMMIT();
        CP_WAIT1();
        __syncthreads();

        const uint32_t stg = sbase + (it & 1) * STAGE_BYTES;
        const uint32_t ah_b = stg + OFF_AH, al_b = stg + OFF_AL;
        const uint32_t bh_b = stg + OFF_BH, bl_b = stg + OFF_BL;

#pragma unroll
        for (int kk = 0; kk < BK; kk += 16) {
            // A fragments: 4 m-tiles x (hi, lo)
            uint32_t ah[4][4], al[4][4];
            {
                uint32_t aoff = ((wm + (lane & 15)) * LDS + kk + (lane >> 4) * 8) * 2;
#pragma unroll
                for (int mt = 0; mt < 4; ++mt) {
                    uint32_t adr = aoff + mt * 16 * LDS * 2;
                    LDMX4(ah[mt][0], ah[mt][1], ah[mt][2], ah[mt][3], ah_b + adr);
                    LDMX4(al[mt][0], al[mt][1], al[mt][2], al[mt][3], al_b + adr);
                }
            }
            // B fragments: 4 n-tiles x (hi, lo); x4 loads cover 2 n-tiles each
            uint32_t bh[4][2], bl[4][2];
            {
                int g = lane >> 3;
                uint32_t boff = ((wn + (g >> 1) * 8 + (lane & 7)) * LDS + kk + (g & 1) * 8) * 2;
#pragma unroll
                for (int p = 0; p < 2; ++p) {
                    uint32_t adr = boff + p * 16 * LDS * 2;
                    LDMX4(bh[2 * p][0], bh[2 * p][1], bh[2 * p + 1][0], bh[2 * p + 1][1], bh_b + adr);
                    LDMX4(bl[2 * p][0], bl[2 * p][1], bl[2 * p + 1][0], bl[2 * p + 1][1], bl_b + adr);
                }
            }
#pragma unroll
            for (int mt = 0; mt < 4; ++mt)
#pragma unroll
                for (int nt = 0; nt < 4; ++nt) {
                    MMA16816(acc[mt][nt], ah[mt], bh[nt]);
                    MMA16816(acc[mt][nt], ah[mt], bl[nt]);
                    MMA16816(acc[mt][nt], al[mt], bh[nt]);
                }
        }
        __syncthreads();
    }

    // epilogue: + bias, store float2 per fragment half
#pragma unroll
    for (int mt = 0; mt < 4; ++mt) {
#pragma unroll
        for (int nt = 0; nt < 4; ++nt) {
            int row = m0 + wm + mt * 16 + (lane >> 2);
            int col = n0 + wn + nt * 8 + (lane & 3) * 2;
            float2 bv = *(const float2*)(g_bf + col);
            if (row < Nn) {
                float2 o; o.x = acc[mt][nt][0] + bv.x; o.y = acc[mt][nt][1] + bv.y;
                *(float2*)(g_QKV + (size_t)row * INNER + col) = o;
            }
            if (row + 8 < Nn) {
                float2 o; o.x = acc[mt][nt][2] + bv.x; o.y = acc[mt][nt][3] + bv.y;
                *(float2*)(g_QKV + (size_t)(row + 8) * INNER + col) = o;
            }
        }
    }
}

// ---------------- CSR build ----------------------------------------------------
__global__ void hist_kernel(const int* __restrict__ dst, int E) {
    int e = blockIdx.x * blockDim.x + threadIdx.x;
    if (e < E) atomicAdd(&g_deg[dst[e]], 1);
}

// single-block shuffle-based exclusive scan: 1024 threads x 4 elements/tile
__global__ __launch_bounds__(1024) void scan_kernel(int n) {
    __shared__ int wsum[32];
    __shared__ int carry_s;
    const int t = threadIdx.x, lane = t & 31, wid = t >> 5;
    if (t == 0) carry_s = 0;
    __syncthreads();
    const int nTiles = (n + 4095) >> 12;
    for (int tile = 0; tile < nTiles; ++tile) {
        int idx = (tile << 12) + t * 4;
        int4 v = make_int4(0, 0, 0, 0);
        if (idx + 3 < n) v = *(const int4*)(g_deg + idx);
        else {
            if (idx + 0 < n) v.x = g_deg[idx];
            if (idx + 1 < n) v.y = g_deg[idx + 1];
            if (idx + 2 < n) v.z = g_deg[idx + 2];
        }
        int s = v.x + v.y + v.z + v.w;
        int incl = s;
#pragma unroll
        for (int d = 1; d < 32; d <<= 1) {
            int o = __shfl_up_sync(0xffffffffu, incl, d);
            if (lane >= d) incl += o;
        }
        if (lane == 31) wsum[wid] = incl;
        __syncthreads();
        if (wid == 0) {
            int ws = wsum[lane];
            int wincl = ws;
#pragma unroll
            for (int d = 1; d < 32; d <<= 1) {
                int o = __shfl_up_sync(0xffffffffu, wincl, d);
                if (lane >= d) wincl += o;
            }
            wsum[lane] = wincl - ws;   // exclusive warp prefix
        }
        __syncthreads();
        int excl = carry_s + wsum[wid] + (incl - s);
        int e0 = excl, e1 = e0 + v.x, e2 = e1 + v.y, e3 = e2 + v.z;
        if (idx + 0 < n) { g_off[idx + 0] = e0; g_cur[idx + 0] = e0; }
        if (idx + 1 < n) { g_off[idx + 1] = e1; g_cur[idx + 1] = e1; }
        if (idx + 2 < n) { g_off[idx + 2] = e2; g_cur[idx + 2] = e2; }
        if (idx + 3 < n) { g_off[idx + 3] = e3; g_cur[idx + 3] = e3; }
        __syncthreads();
        if (t == 1023) carry_s += wsum[31] + incl;
        __syncthreads();
    }
    if (t == 0) g_off[n] = carry_s;
}

// store src node id directly (kills one indirection in the attention hot loop)
__global__ void scatter_kernel(const int* __restrict__ dst, const int* __restrict__ src,
                               int E) {
    int e = blockIdx.x * blockDim.x + threadIdx.x;
    if (e < E) {
        int p = atomicAdd(&g_cur[dst[e]], 1);
        g_sperm[p] = src[e];
    }
}

// ---------------- single-pass online-softmax attention ------------------------
// one warp per dst node; lane l owns output dims [8l,8l+8); head = l>>2.
__global__ __launch_bounds__(256) void attn_kernel(float* __restrict__ out, int n_nodes) {
    int gwarp = (blockIdx.x * blockDim.x + threadIdx.x) >> 5;
    int lane = threadIdx.x & 31;
    if (gwarp >= n_nodes) return;
    const int rs = g_off[gwarp];
    const int re = g_off[gwarp + 1];

    const float4* kp = (const float4*)(g_QKV + (size_t)gwarp * INNER + 256 + lane * 8);
    const float4 k0 = kp[0], k1 = kp[1];

    float m = -INFINITY, z = 0.f;
    float4 a0 = make_float4(0.f, 0.f, 0.f, 0.f);
    float4 a1 = make_float4(0.f, 0.f, 0.f, 0.f);

    // prefetch first index: the index load heads the dependent chain
    int s = (rs < re) ? __ldg(&g_sperm[rs]) : 0;

    for (int i = rs; i < re; ++i) {
        int s_next = (i + 1 < re) ? __ldg(&g_sperm[i + 1]) : 0;

        const float4* qp = (const float4*)(g_QKV + (size_t)s * INNER + lane * 8);
        const float4* vp = (const float4*)(g_QKV + (size_t)s * INNER + 512 + lane * 8);
        float4 q0 = qp[0], q1 = qp[1];
        float4 v0 = vp[0], v1 = vp[1];

        float p = q0.x * k0.x + q0.y * k0.y + q0.z * k0.z + q0.w * k0.w
                + q1.x * k1.x + q1.y * k1.y + q1.z * k1.z + q1.w * k1.w;
        p += __shfl_xor_sync(0xffffffffu, p, 1);
        p += __shfl_xor_sync(0xffffffffu, p, 2);
        float sc = p * 0.17677669529663689f;   // 1/sqrt(32)

        float nm = fmaxf(m, sc);
        float scale = __expf(m - nm);          // first iter: exp(-inf)=0
        float wgt = __expf(sc - nm);
        m = nm;
        z = fmaf(z, scale, wgt);
        a0.x = fmaf(a0.x, scale, v0.x * wgt); a0.y = fmaf(a0.y, scale, v0.y * wgt);
        a0.z = fmaf(a0.z, scale, v0.z * wgt); a0.w = fmaf(a0.w, scale, v0.w * wgt);
        a1.x = fmaf(a1.x, scale, v1.x * wgt); a1.y = fmaf(a1.y, scale, v1.y * wgt);
        a1.z = fmaf(a1.z, scale, v1.z * wgt); a1.w = fmaf(a1.w, scale, v1.w * wgt);

        s = s_next;
    }
    float inv = 1.f / fmaxf(z, 1e-16f);
    float4* op = (float4*)(out + (size_t)gwarp * 256 + lane * 8);
    op[0] = make_float4(a0.x * inv, a0.y * inv, a0.z * inv, a0.w * inv);
    op[1] = make_float4(a1.x * inv, a1.y * inv, a1.z * inv, a1.w * inv);
}

// ---------------- launch -------------------------------------------------------
extern "C" void kernel_launch(void* const* d_in, const int* in_sizes, int n_in,
                              void* d_out, int out_size) {
    const float* x  = (const float*)d_in[0];
    const float* Wq = (const float*)d_in[1];
    const float* bq = (const float*)d_in[2];
    const float* Wk = (const float*)d_in[3];
    const float* bk = (const float*)d_in[4];
    const float* Wv = (const float*)d_in[5];
    const float* bv = (const float*)d_in[6];
    const int* src  = (const int*)d_in[7];
    const int* dst  = (const int*)d_in[8];
    float* out = (float*)d_out;

    const int N = in_sizes[0] / DIM;
    const int E = in_sizes[7];

    cudaFuncSetAttribute(gemm_mma_kernel,
                         cudaFuncAttributeMaxDynamicSharedMemorySize, GT_SMEM);

    // weights + bias + deg-zero; x split
    prep_w_kernel<<<(INNER * DIM + 255) / 256, 256>>>(Wq, bq, Wk, bk, Wv, bv, N);
    conv_x_kernel<<<(N * (DIM / 4) + 255) / 256, 256>>>(x, N * (DIM / 4));

    // CSR by dst
    hist_kernel<<<(E + 255) / 256, 256>>>(dst, E);
    scan_kernel<<<1, 1024>>>(N);
    scatter_kernel<<<(E + 255) / 256, 256>>>(dst, src, E);

    // fused QKV projection on tensor cores (mma.sync, cp.async pipelined)
    dim3 ggrid((N + 127) / 128, INNER / 128);
    gemm_mma_kernel<<<ggrid, 256, GT_SMEM>>>(N);

    // warp-per-node single-pass attention
    attn_kernel<<<(N + 7) / 8, 256>>>(out, N);
}

// round 10
// speedup vs baseline: 1.9865x; 1.1202x over previous
#include <cuda_runtime.h>
#include <cuda_bf16.h>
#include <math.h>
#include <stdint.h>

#define DIM 256
#define INNER 768           // Q|K|V concatenated
#define HEADS 8
#define NMAX 50000
#define EMAX 800000

// ---------------- device scratch (static: allocation-free) --------------------
__device__ float          g_QKV[(size_t)NMAX * INNER];   // row: [q(256)|k(256)|v(256)]
__device__ __nv_bfloat16  g_xh[(size_t)NMAX * DIM];
__device__ __nv_bfloat16  g_xl[(size_t)NMAX * DIM];
__device__ __nv_bfloat16  g_wth[INNER * DIM];            // W^T hi: [n][k]
__device__ __nv_bfloat16  g_wtl[INNER * DIM];            // W^T lo
__device__ float          g_bf[INNER];
__device__ __align__(16) int g_deg[NMAX];
__device__ int            g_off[NMAX + 1];
__device__ int            g_cur[NMAX];
__device__ int            g_sperm[EMAX];   // src node id, permuted into dst-CSR order

__device__ __forceinline__ uint32_t smem_u32(const void* p) {
    uint32_t a;
    asm("{ .reg .u64 t; cvta.to.shared.u64 t, %1; cvt.u32.u64 %0, t; }" : "=r"(a) : "l"(p));
    return a;
}

// ---------------- prep: W^T hi/lo + bias --------------------------------------
__global__ void prep_w_kernel(const float* __restrict__ Wq, const float* __restrict__ bq,
                              const float* __restrict__ Wk, const float* __restrict__ bk,
                              const float* __restrict__ Wv, const float* __restrict__ bv) {
    int idx = blockIdx.x * blockDim.x + threadIdx.x;
    if (idx < INNER * DIM) {
        int n = idx >> 8, k = idx & 255;
        float w = (n < 256) ? Wq[k * 256 + n]
                : (n < 512) ? Wk[k * 256 + (n - 256)]
                            : Wv[k * 256 + (n - 512)];
        __nv_bfloat16 h = __float2bfloat16(w);
        __nv_bfloat16 l = __float2bfloat16(w - __bfloat162float(h));
        g_wth[idx] = h;   // layout [n][k] == idx
        g_wtl[idx] = l;
    }
    if (idx < INNER) {
        g_bf[idx] = (idx < 256) ? bq[idx] : (idx < 512) ? bk[idx - 256] : bv[idx - 512];
    }
}

__global__ void zero_deg_kernel(int n) {
    int i = blockIdx.x * blockDim.x + threadIdx.x;
    if (i < n) g_deg[i] = 0;
}

// ---------------- x -> bf16 hi/lo ----------------------------------------------
__global__ void conv_x_kernel(const float* __restrict__ x, int total4) {
    int i = blockIdx.x * blockDim.x + threadIdx.x;
    if (i >= total4) return;
    float4 v = ((const float4*)x)[i];
    float f[4] = {v.x, v.y, v.z, v.w};
    __nv_bfloat16 h[4], l[4];
#pragma unroll
    for (int j = 0; j < 4; ++j) {
        h[j] = __float2bfloat16(f[j]);
        l[j] = __float2bfloat16(f[j] - __bfloat162float(h[j]));
    }
    __nv_bfloat162* ph = (__nv_bfloat162*)g_xh + 2 * (size_t)i;
    __nv_bfloat162* pl = (__nv_bfloat162*)g_xl + 2 * (size_t)i;
    ph[0] = __halves2bfloat162(h[0], h[1]);
    ph[1] = __halves2bfloat162(h[2], h[3]);
    pl[0] = __halves2bfloat162(l[0], l[1]);
    pl[1] = __halves2bfloat162(l[2], l[3]);
}

// ---------------- mma.sync bf16 GEMM: g_QKV[M,768] = x @ W + b ----------------
// CTA 128x128, BK=32, 8 warps (2x4), warp tile 64x32.
// Split fp32: C = Ah*Bh + Ah*Bl + Al*Bh.  cp.async 2-stage pipeline.
#define BK 32
#define LDS 40            // smem row stride (bf16): 32 + 8 pad -> 80B
#define ARR_BYTES (128 * LDS * 2)      // 10240
#define OFF_AH 0
#define OFF_AL ARR_BYTES
#define OFF_BH (2 * ARR_BYTES)
#define OFF_BL (3 * ARR_BYTES)
#define STAGE_BYTES (4 * ARR_BYTES)    // 40960
#define GT_SMEM (2 * STAGE_BYTES)      // 81920

#define LDMX4(r0, r1, r2, r3, a)                                              \
    asm volatile("ldmatrix.sync.aligned.m8n8.x4.shared.b16 {%0,%1,%2,%3}, [%4];" \
        : "=r"(r0), "=r"(r1), "=r"(r2), "=r"(r3) : "r"(a))

#define MMA16816(c, A, B)                                                     \
    asm volatile("mma.sync.aligned.m16n8k16.row.col.f32.bf16.bf16.f32 "       \
        "{%0,%1,%2,%3}, {%4,%5,%6,%7}, {%8,%9}, {%0,%1,%2,%3};"               \
        : "+f"((c)[0]), "+f"((c)[1]), "+f"((c)[2]), "+f"((c)[3])              \
        : "r"((A)[0]), "r"((A)[1]), "r"((A)[2]), "r"((A)[3]),                 \
          "r"((B)[0]), "r"((B)[1]))

__device__ __forceinline__ void cp16(uint32_t d, const void* s, int sz) {
    asm volatile("cp.async.cg.shared.global [%0], [%1], 16, %2;"
                 :: "r"(d), "l"(s), "r"(sz));
}
#define CP_COMMIT() asm volatile("cp.async.commit_group;" ::: "memory")
#define CP_WAIT1()  asm volatile("cp.async.wait_group 1;" ::: "memory")

__global__ __launch_bounds__(256) void gemm_mma_kernel(int Nn) {
    extern __shared__ __align__(16) char dynsmem[];

    const int t = threadIdx.x;
    const int lane = t & 31;
    const int w = t >> 5;
    const int wm = (w & 1) * 64;     // warp row offset in CTA tile
    const int wn = (w >> 1) * 32;    // warp col offset
    const int m0 = blockIdx.x * 128;
    const int n0 = blockIdx.y * 128;
    const uint32_t sbase = smem_u32(dynsmem);

    float acc[4][4][4];
#pragma unroll
    for (int i = 0; i < 4; ++i)
#pragma unroll
        for (int j = 0; j < 4; ++j)
#pragma unroll
            for (int c = 0; c < 4; ++c) acc[i][j][c] = 0.f;

    // gmem->smem indices: 2 threads per row, 16 bf16 (32B = 2 cp.async) each
    const int ldr = t >> 1;               // 0..127
    const int ldc = (t & 1) * 16;         // 0 or 16
    const int s_byte = (ldr * LDS + ldc) * 2;
    const int asz = ((m0 + ldr) < Nn) ? 16 : 0;   // zero-fill M tail

    const __nv_bfloat16* gah = g_xh  + (size_t)(m0 + ldr) * DIM + ldc;
    const __nv_bfloat16* gal = g_xl  + (size_t)(m0 + ldr) * DIM + ldc;
    const __nv_bfloat16* gbh = g_wth + (size_t)(n0 + ldr) * DIM + ldc;
    const __nv_bfloat16* gbl = g_wtl + (size_t)(n0 + ldr) * DIM + ldc;

#define LOAD_STAGE(stg, k0) do {                                              \
        uint32_t sb_ = sbase + (stg) * STAGE_BYTES;                           \
        cp16(sb_ + OFF_AH + s_byte,      gah + (k0),     asz);                \
        cp16(sb_ + OFF_AH + s_byte + 16, gah + (k0) + 8, asz);                \
        cp16(sb_ + OFF_AL + s_byte,      gal + (k0),     asz);                \
        cp16(sb_ + OFF_AL + s_byte + 16, gal + (k0) + 8, asz);                \
        cp16(sb_ + OFF_BH + s_byte,      gbh + (k0),     16);                 \
        cp16(sb_ + OFF_BH + s_byte + 16, gbh + (k0) + 8, 16);                 \
        cp16(sb_ + OFF_BL + s_byte,      gbl + (k0),     16);                 \
        cp16(sb_ + OFF_BL + s_byte + 16, gbl + (k0) + 8, 16);                 \
    } while (0)

    LOAD_STAGE(0, 0);
    CP_COMMIT();

#pragma unroll 1
    for (int it = 0; it < DIM / BK; ++it) {
        if (it + 1 < DIM / BK) LOAD_STAGE((it + 1) & 1, (it + 1) * BK);
        CP_COMMIT();
        CP_WAIT1();
        __syncthreads();

        const uint32_t stg = sbase + (it & 1) * STAGE_BYTES;
        const uint32_t ah_b = stg + OFF_AH, al_b = stg + OFF_AL;
        const uint32_t bh_b = stg + OFF_BH, bl_b = stg + OFF_BL;

#pragma unroll
        for (int kk = 0; kk < BK; kk += 16) {
            // A fragments: 4 m-tiles x (hi, lo)
            uint32_t ah[4][4], al[4][4];
            {
                uint32_t aoff = ((wm + (lane & 15)) * LDS + kk + (lane >> 4) * 8) * 2;
#pragma unroll
                for (int mt = 0; mt < 4; ++mt) {
                    uint32_t adr = aoff + mt * 16 * LDS * 2;
                    LDMX4(ah[mt][0], ah[mt][1], ah[mt][2], ah[mt][3], ah_b + adr);
                    LDMX4(al[mt][0], al[mt][1], al[mt][2], al[mt][3], al_b + adr);
                }
            }
            // B fragments: 4 n-tiles x (hi, lo); x4 loads cover 2 n-tiles each
            uint32_t bh[4][2], bl[4][2];
            {
                int g = lane >> 3;
                uint32_t boff = ((wn + (g >> 1) * 8 + (lane & 7)) * LDS + kk + (g & 1) * 8) * 2;
#pragma unroll
                for (int p = 0; p < 2; ++p) {
                    uint32_t adr = boff + p * 16 * LDS * 2;
                    LDMX4(bh[2 * p][0], bh[2 * p][1], bh[2 * p + 1][0], bh[2 * p + 1][1], bh_b + adr);
                    LDMX4(bl[2 * p][0], bl[2 * p][1], bl[2 * p + 1][0], bl[2 * p + 1][1], bl_b + adr);
                }
            }
#pragma unroll
            for (int mt = 0; mt < 4; ++mt)
#pragma unroll
                for (int nt = 0; nt < 4; ++nt) {
                    MMA16816(acc[mt][nt], ah[mt], bh[nt]);
                    MMA16816(acc[mt][nt], ah[mt], bl[nt]);
                    MMA16816(acc[mt][nt], al[mt], bh[nt]);
                }
        }
        __syncthreads();
    }

    // epilogue: + bias, store float2 per fragment half
#pragma unroll
    for (int mt = 0; mt < 4; ++mt) {
#pragma unroll
        for (int nt = 0; nt < 4; ++nt) {
            int row = m0 + wm + mt * 16 + (lane >> 2);
            int col = n0 + wn + nt * 8 + (lane & 3) * 2;
            float2 bv = *(const float2*)(g_bf + col);
            if (row < Nn) {
                float2 o; o.x = acc[mt][nt][0] + bv.x; o.y = acc[mt][nt][1] + bv.y;
                *(float2*)(g_QKV + (size_t)row * INNER + col) = o;
            }
            if (row + 8 < Nn) {
                float2 o; o.x = acc[mt][nt][2] + bv.x; o.y = acc[mt][nt][3] + bv.y;
                *(float2*)(g_QKV + (size_t)(row + 8) * INNER + col) = o;
            }
        }
    }
}

// ---------------- CSR build ----------------------------------------------------
__global__ void hist_kernel(const int* __restrict__ dst, int E) {
    int e = blockIdx.x * blockDim.x + threadIdx.x;
    if (e < E) atomicAdd(&g_deg[dst[e]], 1);
}

// single-block shuffle-based exclusive scan: 1024 threads x 4 elements/tile
__global__ __launch_bounds__(1024) void scan_kernel(int n) {
    __shared__ int wsum[32];
    __shared__ int carry_s;
    const int t = threadIdx.x, lane = t & 31, wid = t >> 5;
    if (t == 0) carry_s = 0;
    __syncthreads();
    const int nTiles = (n + 4095) >> 12;
    for (int tile = 0; tile < nTiles; ++tile) {
        int idx = (tile << 12) + t * 4;
        int4 v = make_int4(0, 0, 0, 0);
        if (idx + 3 < n) v = *(const int4*)(g_deg + idx);
        else {
            if (idx + 0 < n) v.x = g_deg[idx];
            if (idx + 1 < n) v.y = g_deg[idx + 1];
            if (idx + 2 < n) v.z = g_deg[idx + 2];
        }
        int s = v.x + v.y + v.z + v.w;
        int incl = s;
#pragma unroll
        for (int d = 1; d < 32; d <<= 1) {
            int o = __shfl_up_sync(0xffffffffu, incl, d);
            if (lane >= d) incl += o;
        }
        if (lane == 31) wsum[wid] = incl;
        __syncthreads();
        if (wid == 0) {
            int ws = wsum[lane];
            int wincl = ws;
#pragma unroll
            for (int d = 1; d < 32; d <<= 1) {
                int o = __shfl_up_sync(0xffffffffu, wincl, d);
                if (lane >= d) wincl += o;
            }
            wsum[lane] = wincl - ws;   // exclusive warp prefix
        }
        __syncthreads();
        int excl = carry_s + wsum[wid] + (incl - s);
        int e0 = excl, e1 = e0 + v.x, e2 = e1 + v.y, e3 = e2 + v.z;
        if (idx + 0 < n) { g_off[idx + 0] = e0; g_cur[idx + 0] = e0; }
        if (idx + 1 < n) { g_off[idx + 1] = e1; g_cur[idx + 1] = e1; }
        if (idx + 2 < n) { g_off[idx + 2] = e2; g_cur[idx + 2] = e2; }
        if (idx + 3 < n) { g_off[idx + 3] = e3; g_cur[idx + 3] = e3; }
        __syncthreads();
        if (t == 1023) carry_s += wsum[31] + incl;
        __syncthreads();
    }
    if (t == 0) g_off[n] = carry_s;
}

// store src node id directly (kills one indirection in the attention hot loop)
__global__ void scatter_kernel(const int* __restrict__ dst, const int* __restrict__ src,
                               int E) {
    int e = blockIdx.x * blockDim.x + threadIdx.x;
    if (e < E) {
        int p = atomicAdd(&g_cur[dst[e]], 1);
        g_sperm[p] = src[e];
    }
}

// ---------------- single-pass online-softmax attention ------------------------
// one warp per dst node; lane l owns output dims [8l,8l+8); head = l>>2.
__global__ __launch_bounds__(256) void attn_kernel(float* __restrict__ out, int n_nodes) {
    int gwarp = (blockIdx.x * blockDim.x + threadIdx.x) >> 5;
    int lane = threadIdx.x & 31;
    if (gwarp >= n_nodes) return;
    const int rs = g_off[gwarp];
    const int re = g_off[gwarp + 1];

    const float4* kp = (const float4*)(g_QKV + (size_t)gwarp * INNER + 256 + lane * 8);
    const float4 k0 = kp[0], k1 = kp[1];

    float m = -INFINITY, z = 0.f;
    float4 a0 = make_float4(0.f, 0.f, 0.f, 0.f);
    float4 a1 = make_float4(0.f, 0.f, 0.f, 0.f);

    // prefetch first index: the index load heads the dependent chain
    int s = (rs < re) ? __ldg(&g_sperm[rs]) : 0;

    for (int i = rs; i < re; ++i) {
        int s_next = (i + 1 < re) ? __ldg(&g_sperm[i + 1]) : 0;

        const float4* qp = (const float4*)(g_QKV + (size_t)s * INNER + lane * 8);
        const float4* vp = (const float4*)(g_QKV + (size_t)s * INNER + 512 + lane * 8);
        float4 q0 = qp[0], q1 = qp[1];
        float4 v0 = vp[0], v1 = vp[1];

        float p = q0.x * k0.x + q0.y * k0.y + q0.z * k0.z + q0.w * k0.w
                + q1.x * k1.x + q1.y * k1.y + q1.z * k1.z + q1.w * k1.w;
        p += __shfl_xor_sync(0xffffffffu, p, 1);
        p += __shfl_xor_sync(0xffffffffu, p, 2);
        float sc = p * 0.17677669529663689f;   // 1/sqrt(32)

        float nm = fmaxf(m, sc);
        float scale = __expf(m - nm);          // first iter: exp(-inf)=0
        float wgt = __expf(sc - nm);
        m = nm;
        z = fmaf(z, scale, wgt);
        a0.x = fmaf(a0.x, scale, v0.x * wgt); a0.y = fmaf(a0.y, scale, v0.y * wgt);
        a0.z = fmaf(a0.z, scale, v0.z * wgt); a0.w = fmaf(a0.w, scale, v0.w * wgt);
        a1.x = fmaf(a1.x, scale, v1.x * wgt); a1.y = fmaf(a1.y, scale, v1.y * wgt);
        a1.z = fmaf(a1.z, scale, v1.z * wgt); a1.w = fmaf(a1.w, scale, v1.w * wgt);

        s = s_next;
    }
    float inv = 1.f / fmaxf(z, 1e-16f);
    float4* op = (float4*)(out + (size_t)gwarp * 256 + lane * 8);
    op[0] = make_float4(a0.x * inv, a0.y * inv, a0.z * inv, a0.w * inv);
    op[1] = make_float4(a1.x * inv, a1.y * inv, a1.z * inv, a1.w * inv);
}

// ---------------- launch: two-stream fork/join ---------------------------------
// Chain A (default stream): prep_w -> conv_x -> gemm        (feeds attn)
// Chain B (side stream):    zero_deg -> hist -> scan -> scatter (feeds attn)
// Both chains are independent until attn; B hides fully under A.
extern "C" void kernel_launch(void* const* d_in, const int* in_sizes, int n_in,
                              void* d_out, int out_size) {
    const float* x  = (const float*)d_in[0];
    const float* Wq = (const float*)d_in[1];
    const float* bq = (const float*)d_in[2];
    const float* Wk = (const float*)d_in[3];
    const float* bk = (const float*)d_in[4];
    const float* Wv = (const float*)d_in[5];
    const float* bv = (const float*)d_in[6];
    const int* src  = (const int*)d_in[7];
    const int* dst  = (const int*)d_in[8];
    float* out = (float*)d_out;

    const int N = in_sizes[0] / DIM;
    const int E = in_sizes[7];

    // one-time host-side resources (no device memory involved)
    static cudaStream_t s_side = nullptr;
    static cudaEvent_t  s_evFork = nullptr, s_evJoin = nullptr;
    static bool s_attrSet = false;
    if (s_side == nullptr) {
        cudaStreamCreateWithFlags(&s_side, cudaStreamNonBlocking);
        cudaEventCreateWithFlags(&s_evFork, cudaEventDisableTiming);
        cudaEventCreateWithFlags(&s_evJoin, cudaEventDisableTiming);
    }
    if (!s_attrSet) {
        cudaFuncSetAttribute(gemm_mma_kernel,
                             cudaFuncAttributeMaxDynamicSharedMemorySize, GT_SMEM);
        s_attrSet = true;
    }

    // fork: side stream picks up from the capture/default stream
    cudaEventRecord(s_evFork, 0);
    cudaStreamWaitEvent(s_side, s_evFork, 0);

    // ---- chain B (side): CSR by dst ----
    zero_deg_kernel<<<(N + 255) / 256, 256, 0, s_side>>>(N);
    hist_kernel<<<(E + 255) / 256, 256, 0, s_side>>>(dst, E);
    scan_kernel<<<1, 1024, 0, s_side>>>(N);
    scatter_kernel<<<(E + 255) / 256, 256, 0, s_side>>>(dst, src, E);
    cudaEventRecord(s_evJoin, s_side);

    // ---- chain A (default stream): QKV projection ----
    prep_w_kernel<<<(INNER * DIM + 255) / 256, 256>>>(Wq, bq, Wk, bk, Wv, bv);
    conv_x_kernel<<<(N * (DIM / 4) + 255) / 256, 256>>>(x, N * (DIM / 4));
    dim3 ggrid((N + 127) / 128, INNER / 128);
    gemm_mma_kernel<<<ggrid, 256, GT_SMEM>>>(N);

    // join, then attention
    cudaStreamWaitEvent(0, s_evJoin, 0);
    attn_kernel<<<(N + 7) / 8, 256>>>(out, N);
}